// round 1
// baseline (speedup 1.0000x reference)
#include <cuda_runtime.h>
#include <cstdint>

// Problem constants
#define NB   256
#define SEQ  720
#define PRED 720
#define RNK  16
#define CTXD 128
#define HIDD 64
#define ODIM (RNK*(SEQ+PRED))   // 23040
#define AOFF 0                  // A_delta at h[b][p*16+r]
#define BOFF (RNK*PRED)         // 11520, B_delta at h[b][11520 + r*720 + s]
#define YSZ  (NB*PRED)          // 184320

// Scratch (device globals: allocation-free)
__device__ float g_hidden[NB*HIDD];
__device__ float g_h[(size_t)NB*ODIM];   // hyper-MLP output, 23.6 MB
__device__ float g_t[NB*RNK];

// ---------------- packed f32x2 helpers ----------------
__device__ __forceinline__ unsigned long long ffma2(unsigned long long a,
                                                    unsigned long long b,
                                                    unsigned long long c) {
    unsigned long long d;
    asm("fma.rn.f32x2 %0, %1, %2, %3;" : "=l"(d) : "l"(a), "l"(b), "l"(c));
    return d;
}
__device__ __forceinline__ unsigned long long dup2(float a) {
    unsigned long long d;
    asm("mov.b64 %0, {%1, %1};" : "=l"(d) : "f"(a));
    return d;
}
__device__ __forceinline__ float4 u2f4(unsigned long long a, unsigned long long b) {
    union { ulonglong2 u; float4 f; } c; c.u.x = a; c.u.y = b; return c.f;
}

// ---------------- kernel 1a: hidden = relu(ctx @ W1^T + b1) ----------------
__global__ void hidden_kernel(const float* __restrict__ ctx,
                              const float* __restrict__ W1,
                              const float* __restrict__ b1) {
    __shared__ float sc[CTXD];
    int b = blockIdx.x;
    int t = threadIdx.x;               // 128 threads
    sc[t] = ctx[b*CTXD + t];
    __syncthreads();
    if (t < HIDD) {
        float s = b1[t];
        const float* w = W1 + t*CTXD;
        #pragma unroll 16
        for (int k = 0; k < CTXD; ++k) s += w[k]*sc[k];
        g_hidden[b*HIDD + t] = fmaxf(s, 0.f);
    }
}

// ---------------- kernel 1b: h = hidden @ W2^T + b2  (M=23040,N=256,K=64) ----
// f32x2: output pairs packed along the o-dimension (contiguous in g_h[b][o]).
__global__ void __launch_bounds__(256) mlp2_kernel(const float* __restrict__ W2,
                                                   const float* __restrict__ b2) {
    __shared__ float sW2T[64*68];   // [k][o_local] (transposed tile)
    __shared__ float sHT [64*68];   // [k][b_local]
    const int tx = threadIdx.x, ty = threadIdx.y;
    const int tid = ty*16 + tx;
    const int o0 = blockIdx.x*64, b0 = blockIdx.y*64;

    for (int idx = tid; idx < 4096; idx += 256) {
        int i = idx >> 6, k = idx & 63;
        sW2T[k*68 + i] = W2[(size_t)(o0+i)*HIDD + k];
        sHT [k*68 + i] = g_hidden[(b0+i)*HIDD + k];
    }
    __syncthreads();

    unsigned long long acc[4][2];
    #pragma unroll
    for (int j = 0; j < 4; ++j) { acc[j][0] = 0ull; acc[j][1] = 0ull; }

    #pragma unroll 16
    for (int k = 0; k < 64; ++k) {
        float4 hb = *reinterpret_cast<const float4*>(&sHT[k*68 + tx*4]);
        ulonglong2 w = *reinterpret_cast<const ulonglong2*>(&sW2T[k*68 + ty*4]);
        const float hv[4] = {hb.x, hb.y, hb.z, hb.w};
        #pragma unroll
        for (int j = 0; j < 4; ++j) {
            unsigned long long ap = dup2(hv[j]);
            acc[j][0] = ffma2(ap, w.x, acc[j][0]);
            acc[j][1] = ffma2(ap, w.y, acc[j][1]);
        }
    }
    float4 bias = *reinterpret_cast<const float4*>(&b2[o0 + ty*4]);
    #pragma unroll
    for (int j = 0; j < 4; ++j) {
        float4 v = u2f4(acc[j][0], acc[j][1]);
        v.x += bias.x; v.y += bias.y; v.z += bias.z; v.w += bias.w;
        *reinterpret_cast<float4*>(&g_h[(size_t)(b0 + tx*4 + j)*ODIM + o0 + ty*4]) = v;
    }
}

// ---------------- kernel 2: t[b][r] = B_delta[b,r,:] @ x[b,:] ----------------
__global__ void t_kernel(const float* __restrict__ x) {
    int b = blockIdx.x;
    int tid = threadIdx.x;            // 256 threads
    int r = tid >> 4, l = tid & 15;
    const float* bd = g_h + (size_t)b*ODIM + BOFF + r*SEQ;
    const float* xb = x + b*SEQ;
    float s = 0.f;
    for (int i = l; i < SEQ; i += 16) s += bd[i]*xb[i];
    #pragma unroll
    for (int off = 8; off; off >>= 1) s += __shfl_down_sync(0xffffffffu, s, off, 16);
    if (l == 0) g_t[b*RNK + r] = s;
}

// ---------------- kernel 3: y[b][p] = (W@x)[p,b] + A[b,p,:]·t[b,:] -----------
#define YKC 48
__global__ void __launch_bounds__(256) y_kernel(const float* __restrict__ W,
                                                const float* __restrict__ x,
                                                float* __restrict__ y) {
    __shared__ float sWT[YKC*68];   // [k][p_local], zero-padded past p=719
    __shared__ float sXT[YKC*68];   // [k][b_local]
    __shared__ float st [64*16];
    const int tx = threadIdx.x, ty = threadIdx.y;
    const int tid = ty*16 + tx;
    const int p0 = blockIdx.x*64, b0 = blockIdx.y*64;

    for (int idx = tid; idx < 1024; idx += 256) st[idx] = g_t[b0*RNK + idx];

    unsigned long long acc[4][2];
    #pragma unroll
    for (int j = 0; j < 4; ++j) { acc[j][0] = 0ull; acc[j][1] = 0ull; }

    for (int c = 0; c < SEQ/YKC; ++c) {
        int k0 = c*YKC;
        __syncthreads();
        for (int idx = tid; idx < 64*YKC; idx += 256) {
            int i = idx / YKC, kk = idx % YKC;
            sWT[kk*68 + i] = (p0 + i < PRED) ? W[(size_t)(p0+i)*SEQ + k0 + kk] : 0.f;
            sXT[kk*68 + i] = x[(size_t)(b0+i)*SEQ + k0 + kk];
        }
        __syncthreads();
        #pragma unroll 12
        for (int kk = 0; kk < YKC; ++kk) {
            float4 xv = *reinterpret_cast<const float4*>(&sXT[kk*68 + tx*4]);
            ulonglong2 w = *reinterpret_cast<const ulonglong2*>(&sWT[kk*68 + ty*4]);
            const float xs[4] = {xv.x, xv.y, xv.z, xv.w};
            #pragma unroll
            for (int j = 0; j < 4; ++j) {
                unsigned long long ap = dup2(xs[j]);
                acc[j][0] = ffma2(ap, w.x, acc[j][0]);
                acc[j][1] = ffma2(ap, w.y, acc[j][1]);
            }
        }
    }
    if (p0 + ty*4 + 3 < PRED) {
        #pragma unroll
        for (int j = 0; j < 4; ++j) {
            int b = b0 + tx*4 + j;
            float4 a4 = u2f4(acc[j][0], acc[j][1]);
            const float* ga = g_h + (size_t)b*ODIM + (p0 + ty*4)*RNK; // 4 A rows, contiguous
            const float* tb = &st[(tx*4 + j)*RNK];
            float d0=0.f, d1=0.f, d2=0.f, d3=0.f;
            #pragma unroll
            for (int r = 0; r < RNK; ++r) {
                float tv = tb[r];
                d0 += ga[r      ]*tv;
                d1 += ga[16 + r ]*tv;
                d2 += ga[32 + r ]*tv;
                d3 += ga[48 + r ]*tv;
            }
            float4 o = make_float4(a4.x + d0, a4.y + d1, a4.z + d2, a4.w + d3);
            *reinterpret_cast<float4*>(&y[(size_t)b*PRED + p0 + ty*4]) = o;
        }
    }
}

// ---------------- kernel 4: W_eff = W + A_delta @ B_delta (the big one) ------
// Grid (15,3,6): p-tiles of 48, s-tiles of 240, batch chunks of 43.
// W tile stays in SMEM across the whole batch chunk (kills W L2 re-reads).
// Inner loop per r: 1 LDS.128 (B) + 4 LDS.64 (pre-dup'd A pairs) + 8 FFMA2.
#define TP 48
#define TS 240
#define WEFF_SMEM ((TP*TS + 16*TS)*4 + TP*16*8)   // 67584 bytes

__global__ void __launch_bounds__(256) weff_kernel(const float* __restrict__ W,
                                                   float* __restrict__ weff) {
    extern __shared__ float smem[];
    float*  sW  = smem;                                   // [TP][TS]
    float*  sB  = smem + TP*TS;                           // [16][TS]
    float2* sAp = reinterpret_cast<float2*>(smem + TP*TS + 16*TS); // [TP][16] dup pairs

    const int tx = threadIdx.x, ty = threadIdx.y;         // blockDim (64,4)
    const int tid = ty*64 + tx;
    const int p0 = blockIdx.x * TP;
    const int s0 = blockIdx.y * TS;
    const int b_beg = blockIdx.z * 43;
    const int b_end = min(NB, b_beg + 43);
    const bool active = (tx < TS/4);
    const int scol = tx*4;

    // W tile -> SMEM, once per block
    for (int idx = tid; idx < TP*TS/4; idx += 256) {
        int row = idx / (TS/4), col = idx % (TS/4);
        float4 v = *reinterpret_cast<const float4*>(&W[(size_t)(p0+row)*SEQ + s0 + col*4]);
        *reinterpret_cast<float4*>(&sW[row*TS + col*4]) = v;
    }

    for (int b = b_beg; b < b_end; ++b) {
        const float* hb = g_h + (size_t)b*ODIM;
        // B_delta tile
        for (int idx = tid; idx < 16*TS/4; idx += 256) {
            int r = idx / (TS/4), col = idx % (TS/4);
            float4 v = *reinterpret_cast<const float4*>(&hb[BOFF + r*SEQ + s0 + col*4]);
            *reinterpret_cast<float4*>(&sB[r*TS + col*4]) = v;
        }
        // pre-duplicated A pairs
        for (int idx = tid; idx < TP*16; idx += 256) {
            int p = idx >> 4, r = idx & 15;
            float a = hb[(p0+p)*RNK + r];
            sAp[idx] = make_float2(a, a);
        }
        __syncthreads();

        if (active) {
            #pragma unroll
            for (int pp = 0; pp < TP/16; ++pp) {
                const int prow = pp*16 + ty*4;
                unsigned long long acc[4][2];
                #pragma unroll
                for (int i = 0; i < 4; ++i) {
                    ulonglong2 w = *reinterpret_cast<const ulonglong2*>(&sW[(prow+i)*TS + scol]);
                    acc[i][0] = w.x; acc[i][1] = w.y;
                }
                #pragma unroll
                for (int r = 0; r < RNK; ++r) {
                    ulonglong2 bv = *reinterpret_cast<const ulonglong2*>(&sB[r*TS + scol]);
                    #pragma unroll
                    for (int i = 0; i < 4; ++i) {
                        unsigned long long ap =
                            *reinterpret_cast<const unsigned long long*>(&sAp[(prow+i)*16 + r]);
                        acc[i][0] = ffma2(ap, bv.x, acc[i][0]);
                        acc[i][1] = ffma2(ap, bv.y, acc[i][1]);
                    }
                }
                #pragma unroll
                for (int i = 0; i < 4; ++i) {
                    size_t off = ((size_t)b*PRED + (p0 + prow + i))*SEQ + s0 + scol;
                    ulonglong2 o; o.x = acc[i][0]; o.y = acc[i][1];
                    *reinterpret_cast<ulonglong2*>(&weff[off]) = o;
                }
            }
        }
        __syncthreads();
    }
}

// ---------------- launch ----------------
extern "C" void kernel_launch(void* const* d_in, const int* in_sizes, int n_in,
                              void* d_out, int out_size) {
    const float* x   = (const float*)d_in[0];  // (256,720,1)
    const float* ctx = (const float*)d_in[1];  // (256,128)
    const float* W   = (const float*)d_in[2];  // (720,720)
    const float* W1  = (const float*)d_in[3];  // (64,128)
    const float* b1  = (const float*)d_in[4];  // (64,)
    const float* W2  = (const float*)d_in[5];  // (23040,64)
    const float* b2  = (const float*)d_in[6];  // (23040,)
    float* out  = (float*)d_out;
    float* y    = out;            // first YSZ elements
    float* weff = out + YSZ;      // then W_eff

    hidden_kernel<<<NB, 128>>>(ctx, W1, b1);
    mlp2_kernel<<<dim3(ODIM/64, NB/64), dim3(16,16)>>>(W2, b2);
    t_kernel<<<NB, 256>>>(x);
    y_kernel<<<dim3((PRED+63)/64, NB/64), dim3(16,16)>>>(W, x, y);

    cudaFuncSetAttribute(weff_kernel, cudaFuncAttributeMaxDynamicSharedMemorySize, WEFF_SMEM);
    weff_kernel<<<dim3(PRED/TP, SEQ/TS, 6), dim3(64,4), WEFF_SMEM>>>(W, weff);
}

// round 3
// speedup vs baseline: 1.6830x; 1.6830x over previous
#include <cuda_runtime.h>
#include <cstdint>

// Problem constants
#define NB   256
#define SEQ  720
#define PRED 720
#define RNK  16
#define CTXD 128
#define HIDD 64
#define ODIM (RNK*(SEQ+PRED))   // 23040
#define BOFF (RNK*PRED)         // 11520, B_delta at h[b][11520 + r*720 + s]
#define YSZ  (NB*PRED)          // 184320

// Scratch (device globals: allocation-free). 16B+ alignment for vector/cp.async.
__device__ __align__(128) float g_hidden[NB*HIDD];
__device__ __align__(128) float g_h[(size_t)NB*ODIM];   // hyper-MLP output, 23.6 MB
__device__ __align__(128) float g_t[NB*RNK];

// ---------------- packed f32x2 + async-copy helpers ----------------
__device__ __forceinline__ unsigned long long ffma2(unsigned long long a,
                                                    unsigned long long b,
                                                    unsigned long long c) {
    unsigned long long d;
    asm("fma.rn.f32x2 %0, %1, %2, %3;" : "=l"(d) : "l"(a), "l"(b), "l"(c));
    return d;
}
__device__ __forceinline__ unsigned long long dup2(float a) {
    unsigned long long d;
    asm("mov.b64 %0, {%1, %1};" : "=l"(d) : "f"(a));
    return d;
}
__device__ __forceinline__ float4 u2f4(unsigned long long a, unsigned long long b) {
    union { ulonglong2 u; float4 f; } c; c.u.x = a; c.u.y = b; return c.f;
}
__device__ __forceinline__ void cp16(void* smem_dst, const void* gmem_src) {
    unsigned s = (unsigned)__cvta_generic_to_shared(smem_dst);
    asm volatile("cp.async.cg.shared.global [%0], [%1], 16;" :: "r"(s), "l"(gmem_src));
}
#define CP_COMMIT() asm volatile("cp.async.commit_group;")
#define CP_WAIT0()  asm volatile("cp.async.wait_group 0;")

// ---------------- kernel 1a: hidden = relu(ctx @ W1^T + b1) ----------------
__global__ void hidden_kernel(const float* __restrict__ ctx,
                              const float* __restrict__ W1,
                              const float* __restrict__ b1) {
    __shared__ float sc[CTXD];
    int b = blockIdx.x;
    int t = threadIdx.x;               // 128 threads
    sc[t] = ctx[b*CTXD + t];
    __syncthreads();
    if (t < HIDD) {
        float s = b1[t];
        const float* w = W1 + t*CTXD;
        #pragma unroll 16
        for (int k = 0; k < CTXD; ++k) s += w[k]*sc[k];
        g_hidden[b*HIDD + t] = fmaxf(s, 0.f);
    }
}

// ---------------- kernel 1b: h = hidden @ W2^T + b2  (M=23040,N=256,K=64) ----
__global__ void __launch_bounds__(256) mlp2_kernel(const float* __restrict__ W2,
                                                   const float* __restrict__ b2) {
    __shared__ float sW2T[64*68];   // [k][o_local]
    __shared__ float sHT [64*68];   // [k][b_local]
    const int tx = threadIdx.x, ty = threadIdx.y;
    const int tid = ty*16 + tx;
    const int o0 = blockIdx.x*64, b0 = blockIdx.y*64;

    for (int idx = tid; idx < 4096; idx += 256) {
        int i = idx >> 6, k = idx & 63;
        sW2T[k*68 + i] = W2[(size_t)(o0+i)*HIDD + k];
        sHT [k*68 + i] = g_hidden[(b0+i)*HIDD + k];
    }
    __syncthreads();

    unsigned long long acc[4][2];
    #pragma unroll
    for (int j = 0; j < 4; ++j) { acc[j][0] = 0ull; acc[j][1] = 0ull; }

    #pragma unroll 16
    for (int k = 0; k < 64; ++k) {
        float4 hb = *reinterpret_cast<const float4*>(&sHT[k*68 + tx*4]);
        ulonglong2 w = *reinterpret_cast<const ulonglong2*>(&sW2T[k*68 + ty*4]);
        const float hv[4] = {hb.x, hb.y, hb.z, hb.w};
        #pragma unroll
        for (int j = 0; j < 4; ++j) {
            unsigned long long ap = dup2(hv[j]);
            acc[j][0] = ffma2(ap, w.x, acc[j][0]);
            acc[j][1] = ffma2(ap, w.y, acc[j][1]);
        }
    }
    float4 bias = *reinterpret_cast<const float4*>(&b2[o0 + ty*4]);
    #pragma unroll
    for (int j = 0; j < 4; ++j) {
        float4 v = u2f4(acc[j][0], acc[j][1]);
        v.x += bias.x; v.y += bias.y; v.z += bias.z; v.w += bias.w;
        *reinterpret_cast<float4*>(&g_h[(size_t)(b0 + tx*4 + j)*ODIM + o0 + ty*4]) = v;
    }
}

// ---------------- kernel 2: t[b][r] = B_delta[b,r,:] @ x[b,:] ----------------
__global__ void t_kernel(const float* __restrict__ x) {
    int b = blockIdx.x;
    int tid = threadIdx.x;            // 256 threads
    int r = tid >> 4, l = tid & 15;
    const float* bd = g_h + (size_t)b*ODIM + BOFF + r*SEQ;
    const float* xb = x + b*SEQ;
    float s = 0.f;
    for (int i = l; i < SEQ; i += 16) s += bd[i]*xb[i];
    #pragma unroll
    for (int off = 8; off; off >>= 1) s += __shfl_down_sync(0xffffffffu, s, off, 16);
    if (l == 0) g_t[b*RNK + r] = s;
}

// ---------------- kernel 3: y[b][p] = (W@x)[p,b] + A[b,p,:]·t[b,:] -----------
// Regridded: 16p x 64b tiles, grid (45,4)=180 blocks -> full chip.
#define YKC 48
__global__ void __launch_bounds__(256) y_kernel(const float* __restrict__ W,
                                                const float* __restrict__ x,
                                                float* __restrict__ y) {
    __shared__ float sWT[YKC*16];   // [k][p_local]
    __shared__ float sXT[YKC*68];   // [k][b_local] (padded)
    __shared__ float st [64*RNK];
    const int tx = threadIdx.x;     // 0..63 : batch
    const int ty = threadIdx.y;     // 0..3  : 4 p's each
    const int tid = ty*64 + tx;
    const int p0 = blockIdx.x*16, b0 = blockIdx.y*64;

    for (int idx = tid; idx < 64*RNK; idx += 256) st[idx] = g_t[b0*RNK + idx];

    unsigned long long acc0 = 0ull, acc1 = 0ull;

    for (int c = 0; c < SEQ/YKC; ++c) {
        int k0 = c*YKC;
        __syncthreads();
        for (int idx = tid; idx < 16*YKC; idx += 256) {
            int i = idx / YKC, kk = idx % YKC;
            sWT[kk*16 + i] = W[(size_t)(p0+i)*SEQ + k0 + kk];
        }
        for (int idx = tid; idx < 64*YKC; idx += 256) {
            int i = idx / YKC, kk = idx % YKC;
            sXT[kk*68 + i] = x[(size_t)(b0+i)*SEQ + k0 + kk];
        }
        __syncthreads();
        #pragma unroll 8
        for (int kk = 0; kk < YKC; ++kk) {
            float xv = sXT[kk*68 + tx];
            ulonglong2 w = *reinterpret_cast<const ulonglong2*>(&sWT[kk*16 + ty*4]);
            unsigned long long ap = dup2(xv);
            acc0 = ffma2(ap, w.x, acc0);
            acc1 = ffma2(ap, w.y, acc1);
        }
    }
    // epilogue: + A[b, p, :] . t[b, :]
    {
        int b = b0 + tx;
        float4 a4 = u2f4(acc0, acc1);
        const float* ga = g_h + (size_t)b*ODIM + (p0 + ty*4)*RNK;
        const float* tb = &st[tx*RNK];
        float d0=0.f, d1=0.f, d2=0.f, d3=0.f;
        #pragma unroll
        for (int r = 0; r < RNK; ++r) {
            float tv = tb[r];
            d0 += ga[r      ]*tv;
            d1 += ga[16 + r ]*tv;
            d2 += ga[32 + r ]*tv;
            d3 += ga[48 + r ]*tv;
        }
        float4 o = make_float4(a4.x + d0, a4.y + d1, a4.z + d2, a4.w + d3);
        *reinterpret_cast<float4*>(&y[(size_t)b*PRED + p0 + ty*4]) = o;
    }
}

// ---------------- kernel 4: W_eff = W + A_delta @ B_delta (the big one) ------
// Double-buffered: cp.async prefetch of next batch's B tile + reg-prefetched A,
// one barrier per batch, streaming (__stcs) output stores.
#define TP 48
#define TS 240
#define SB_F (16*TS)                       // 3840 floats per B buffer
#define WEFF_SMEM (TP*TS*4 + 2*SB_F*4 + 2*TP*16*8)   // 89088 bytes

__global__ void __launch_bounds__(256) weff_kernel(const float* __restrict__ W,
                                                   float* __restrict__ weff) {
    extern __shared__ float smem[];
    float*  sW  = smem;                                   // [TP][TS]
    float*  sB  = smem + TP*TS;                           // [2][16][TS]
    float2* sAp = reinterpret_cast<float2*>(smem + TP*TS + 2*SB_F); // [2][TP][16]

    const int tx = threadIdx.x, ty = threadIdx.y;         // blockDim (64,4)
    const int tid = ty*64 + tx;
    const int p0 = blockIdx.x * TP;
    const int s0 = blockIdx.y * TS;
    const int b_beg = blockIdx.z * 43;
    const int b_end = min(NB, b_beg + 43);
    const bool active = (tx < TS/4);
    const int scol = tx*4;

    // W tile -> SMEM, once per block
    for (int idx = tid; idx < TP*TS/4; idx += 256) {
        int row = idx / (TS/4), col = idx % (TS/4);
        float4 v = *reinterpret_cast<const float4*>(&W[(size_t)(p0+row)*SEQ + s0 + col*4]);
        *reinterpret_cast<float4*>(&sW[row*TS + col*4]) = v;
    }

    // prologue: prefetch first batch into buffer 0
    {
        const float* hb0 = g_h + (size_t)b_beg*ODIM;
        for (int idx = tid; idx < 16*TS/4; idx += 256) {
            int r = idx / (TS/4), col = idx % (TS/4);
            cp16(&sB[r*TS + col*4], &hb0[BOFF + r*SEQ + s0 + col*4]);
        }
        CP_COMMIT();
        #pragma unroll
        for (int k = 0; k < 3; ++k) {
            float a = hb0[p0*RNK + tid + k*256];
            sAp[tid + k*256] = make_float2(a, a);
        }
        CP_WAIT0();
    }
    __syncthreads();

    for (int b = b_beg; b < b_end; ++b) {
        const int cur = (b - b_beg) & 1;
        const int nxt = cur ^ 1;
        const bool pf = (b + 1 < b_end);
        float apre[3];

        // issue prefetch for b+1 (cp.async B tile + LDG A into regs)
        if (pf) {
            const float* hbn = g_h + (size_t)(b+1)*ODIM;
            for (int idx = tid; idx < 16*TS/4; idx += 256) {
                int r = idx / (TS/4), col = idx % (TS/4);
                cp16(&sB[nxt*SB_F + r*TS + col*4], &hbn[BOFF + r*SEQ + s0 + col*4]);
            }
            CP_COMMIT();
            #pragma unroll
            for (int k = 0; k < 3; ++k) apre[k] = hbn[p0*RNK + tid + k*256];
        }

        // compute batch b from buffer cur
        if (active) {
            const float*  sBc  = sB  + cur*SB_F;
            const float2* sApc = sAp + cur*(TP*16);
            #pragma unroll
            for (int pp = 0; pp < TP/16; ++pp) {
                const int prow = pp*16 + ty*4;
                unsigned long long acc[4][2];
                #pragma unroll
                for (int i = 0; i < 4; ++i) {
                    ulonglong2 w = *reinterpret_cast<const ulonglong2*>(&sW[(prow+i)*TS + scol]);
                    acc[i][0] = w.x; acc[i][1] = w.y;
                }
                #pragma unroll
                for (int r = 0; r < RNK; ++r) {
                    ulonglong2 bv = *reinterpret_cast<const ulonglong2*>(&sBc[r*TS + scol]);
                    #pragma unroll
                    for (int i = 0; i < 4; ++i) {
                        unsigned long long ap =
                            *reinterpret_cast<const unsigned long long*>(&sApc[(prow+i)*16 + r]);
                        acc[i][0] = ffma2(ap, bv.x, acc[i][0]);
                        acc[i][1] = ffma2(ap, bv.y, acc[i][1]);
                    }
                }
                #pragma unroll
                for (int i = 0; i < 4; ++i) {
                    size_t off = ((size_t)b*PRED + (p0 + prow + i))*SEQ + s0 + scol;
                    __stcs(reinterpret_cast<float4*>(&weff[off]), u2f4(acc[i][0], acc[i][1]));
                }
            }
        }

        if (pf) {
            #pragma unroll
            for (int k = 0; k < 3; ++k)
                sAp[nxt*(TP*16) + tid + k*256] = make_float2(apre[k], apre[k]);
            CP_WAIT0();
        }
        __syncthreads();
    }
}

// ---------------- launch ----------------
extern "C" void kernel_launch(void* const* d_in, const int* in_sizes, int n_in,
                              void* d_out, int out_size) {
    const float* x   = (const float*)d_in[0];  // (256,720,1)
    const float* ctx = (const float*)d_in[1];  // (256,128)
    const float* W   = (const float*)d_in[2];  // (720,720)
    const float* W1  = (const float*)d_in[3];  // (64,128)
    const float* b1  = (const float*)d_in[4];  // (64,)
    const float* W2  = (const float*)d_in[5];  // (23040,64)
    const float* b2  = (const float*)d_in[6];  // (23040,)
    float* out  = (float*)d_out;
    float* y    = out;            // first YSZ elements
    float* weff = out + YSZ;      // then W_eff

    hidden_kernel<<<NB, 128>>>(ctx, W1, b1);
    mlp2_kernel<<<dim3(ODIM/64, NB/64), dim3(16,16)>>>(W2, b2);
    t_kernel<<<NB, 256>>>(x);
    y_kernel<<<dim3(PRED/16, NB/64), dim3(64,4)>>>(W, x, y);

    cudaFuncSetAttribute(weff_kernel, cudaFuncAttributeMaxDynamicSharedMemorySize, WEFF_SMEM);
    weff_kernel<<<dim3(PRED/TP, SEQ/TS, 6), dim3(64,4), WEFF_SMEM>>>(W, weff);
}